// round 9
// baseline (speedup 1.0000x reference)
#include <cuda_runtime.h>
#include <cuda_fp16.h>

// Problem constants (fixed shapes for this problem)
#define Nn    50000
#define FIN   128
#define D1    128           // H1*C1
#define NC    16
#define EMAX  1600000
#define ETMAX (EMAX + Nn)

// ---------------- scratch (device globals; no allocation allowed) ------------
__device__ float4     g_w1t[128 * 32];      // [k][c4] -> w1[c4*4+cc][k]
__device__ float4     g_w2t4[(D1 / 4) * NC];
__device__ __half2    g_xw1h[Nn * 64];      // fp16 gather payload (layer 1)
__device__ float      g_out1[Nn * D1];
__device__ float      g_asrc1[Nn * 2];
__device__ float      g_adst1[Nn * 2];
__device__ __half     g_xw2h[Nn * NC];      // fp16 gather payload (layer 2)
__device__ float      g_asrc2[Nn];
__device__ float      g_adst2[Nn];
__device__ unsigned   g_cnt[Nn];            // invariant: zero at kernel_launch entry
__device__ unsigned   g_off[Nn + 1];
__device__ unsigned   g_cur[Nn];
__device__ int        g_adj[ETMAX];         // CSR by dst: src node ids

__device__ __forceinline__ float lrelu(float a) { return a > 0.f ? a : 0.2f * a; }

// ---------------- tiny prep: weight repacks only -----------------------------
__global__ void k_prep(const float* __restrict__ w1, const float* __restrict__ w2) {
    int i = blockIdx.x * blockDim.x + threadIdx.x;
    if (i < FIN * D1) {
        int c = i / FIN, k = i % FIN;             // w1: [D1][FIN] row-major
        ((float*)g_w1t)[(k * 32 + (c >> 2)) * 4 + (c & 3)] = w1[i];
    }
    if (i < NC * D1) {
        int o = i / D1, k = i % D1;               // w2: [NC][D1]
        ((float*)g_w2t4)[((k >> 2) * NC + o) * 4 + (k & 3)] = w2[i];
    }
}

// ---------------- CSR build (runs on side stream, overlapped with gemm1) -----
__global__ void k_hist(const int* __restrict__ ei, int E, int ET) {
    int e = blockIdx.x * blockDim.x + threadIdx.x;
    if (e >= ET) return;
    int d = (e < E) ? ei[E + e] : (e - E);
    atomicAdd(&g_cnt[d], 1u);
}

__global__ void k_scan(int n) {
    __shared__ unsigned ssum[1024];
    int t = threadIdx.x;
    int chunk = (n + 1023) >> 10;
    int b = t * chunk;
    int e = min(b + chunk, n);
    unsigned sum = 0;
    for (int i = b; i < e; i++) sum += g_cnt[i];
    ssum[t] = sum;
    __syncthreads();
    for (int o = 1; o < 1024; o <<= 1) {
        unsigned v = (t >= o) ? ssum[t - o] : 0u;
        __syncthreads();
        ssum[t] += v;
        __syncthreads();
    }
    unsigned run = (t == 0) ? 0u : ssum[t - 1];
    for (int i = b; i < e; i++) {
        unsigned c = g_cnt[i];
        g_cnt[i] = 0u;                            // restore invariant
        g_off[i] = run;
        g_cur[i] = run;
        run += c;
    }
    if (t == 0) g_off[n] = ssum[1023];
}

__global__ void k_scatter(const int* __restrict__ ei, int E, int ET) {
    int e = blockIdx.x * blockDim.x + threadIdx.x;
    if (e >= ET) return;
    int s, d;
    if (e < E) { s = ei[e]; d = ei[E + e]; } else { s = d = e - E; }
    unsigned pos = atomicAdd(&g_cur[d], 1u);
    g_adj[pos] = s;
}

// ------- layer-1 GEMM (global repacked weights) + att1 dots + fp16 payload ---
__global__ __launch_bounds__(256) void k_gemm1(const float* __restrict__ x,
                                               const float* __restrict__ att_s,
                                               const float* __restrict__ att_d, int n) {
    __shared__ float xs[128 * 33];
    int tid = threadIdx.x;
    int nb  = blockIdx.x * 32;
    for (int idx = tid; idx < 32 * 128; idx += 256) {
        int node = idx >> 7, k = idx & 127;
        xs[k * 33 + node] = (nb + node < n) ? x[(nb + node) * FIN + k] : 0.f;
    }
    __syncthreads();
    int c4 = tid & 31;     // channels c4*4 .. c4*4+3 (lane id)
    int ng = tid >> 5;     // nodes ng*4 .. ng*4+3 (warp id)
    float acc[4][4];
#pragma unroll
    for (int i = 0; i < 4; i++)
#pragma unroll
        for (int j = 0; j < 4; j++) acc[i][j] = 0.f;
#pragma unroll 8
    for (int k = 0; k < 128; k++) {
        float4 w = g_w1t[k * 32 + c4];
        float xv0 = xs[k * 33 + ng * 4 + 0];
        float xv1 = xs[k * 33 + ng * 4 + 1];
        float xv2 = xs[k * 33 + ng * 4 + 2];
        float xv3 = xs[k * 33 + ng * 4 + 3];
        acc[0][0] += xv0 * w.x; acc[0][1] += xv0 * w.y; acc[0][2] += xv0 * w.z; acc[0][3] += xv0 * w.w;
        acc[1][0] += xv1 * w.x; acc[1][1] += xv1 * w.y; acc[1][2] += xv1 * w.z; acc[1][3] += xv1 * w.w;
        acc[2][0] += xv2 * w.x; acc[2][1] += xv2 * w.y; acc[2][2] += xv2 * w.z; acc[2][3] += xv2 * w.w;
        acc[3][0] += xv3 * w.x; acc[3][1] += xv3 * w.y; acc[3][2] += xv3 * w.z; acc[3][3] += xv3 * w.w;
    }
    // fp16 gather payload
#pragma unroll
    for (int i = 0; i < 4; i++) {
        int node = nb + ng * 4 + i;
        if (node < n) {
            g_xw1h[node * 64 + c4 * 2 + 0] = __floats2half2_rn(acc[i][0], acc[i][1]);
            g_xw1h[node * 64 + c4 * 2 + 1] = __floats2half2_rn(acc[i][2], acc[i][3]);
        }
    }
    // fused attention dots: reduce within 16-lane halves (= heads)
    float4 as4 = *(const float4*)&att_s[c4 * 4];
    float4 ad4 = *(const float4*)&att_d[c4 * 4];
#pragma unroll
    for (int i = 0; i < 4; i++) {
        float ps = acc[i][0] * as4.x + acc[i][1] * as4.y + acc[i][2] * as4.z + acc[i][3] * as4.w;
        float pd = acc[i][0] * ad4.x + acc[i][1] * ad4.y + acc[i][2] * ad4.z + acc[i][3] * ad4.w;
#pragma unroll
        for (int o = 8; o >= 1; o >>= 1) {
            ps += __shfl_xor_sync(0xffffffffu, ps, o);
            pd += __shfl_xor_sync(0xffffffffu, pd, o);
        }
        int node = nb + ng * 4 + i;
        if ((c4 & 15) == 0 && node < n) {
            int h = c4 >> 4;
            g_asrc1[node * 2 + h] = ps;
            g_adst1[node * 2 + h] = pd;
        }
    }
}

// ------- layer-1 fused softmax+aggregate: warp/dst, 16-edge pipelined chunks -
__global__ void k_edge1(const float* __restrict__ b1, int n) {
    int gt = blockIdx.x * blockDim.x + threadIdx.x;
    int d  = gt >> 5;
    if (d >= n) return;
    int lane = gt & 31, h = lane >> 4, sub = lane & 15;
    int beg = (int)g_off[d], end = (int)g_off[d + 1];
    float adh = g_adst1[d * 2 + h];
    float4 acc = make_float4(0.f, 0.f, 0.f, 0.f);
    float s = 0.f;
    // chunk 0: lanes 0-15 compute e(head0), lanes 16-31 e(head1), same 16 edges
    int base = beg;
    int msrc = 0; float ex = 0.f;
    {
        int i0 = base + sub;
        if (i0 < end) {
            msrc = g_adj[i0];
            ex = __expf(lrelu(g_asrc1[msrc * 2 + h] + adh));
        }
    }
    while (base < end) {
        int nbase = base + 16;
        int nsrc = 0; float nex = 0.f;
        if (nbase < end) {              // software-pipeline next chunk's dep chain
            int i1 = nbase + sub;
            if (i1 < end) {
                nsrc = g_adj[i1];
                nex = __expf(lrelu(g_asrc1[nsrc * 2 + h] + adh));
            }
        }
        s += ex;
        int cnt = min(16, end - base);
#pragma unroll 8
        for (int j = 0; j < cnt; j++) {
            int   src  = __shfl_sync(0xffffffffu, msrc, j);
            float coef = __shfl_sync(0xffffffffu, ex, j + (h << 4));
            uint2 p = *(const uint2*)&g_xw1h[src * 64 + lane * 2];
            float2 v01 = __half22float2(*(__half2*)&p.x);
            float2 v23 = __half22float2(*(__half2*)&p.y);
            acc.x += v01.x * coef; acc.y += v01.y * coef;
            acc.z += v23.x * coef; acc.w += v23.y * coef;
        }
        msrc = nsrc; ex = nex; base = nbase;
    }
#pragma unroll
    for (int o = 8; o >= 1; o >>= 1)    // per-half sums: lanes<16 -> s0, >=16 -> s1
        s += __shfl_xor_sync(0xffffffffu, s, o);
    float r = 1.f / (s + 1e-16f);
    float4 bb = *(const float4*)&b1[lane * 4];
    *(float4*)&g_out1[d * D1 + lane * 4] =
        make_float4(acc.x * r + bb.x, acc.y * r + bb.y, acc.z * r + bb.z, acc.w * r + bb.w);
}

// ----- layer-2 GEMM (16 nodes/block, relu fused on load) + att2 dots ---------
__global__ __launch_bounds__(256) void k_gemm2(const float* __restrict__ att_s,
                                               const float* __restrict__ att_d, int n) {
    __shared__ float xs[16 * 132];
    int t  = threadIdx.x;            // 256 threads = 16 nodes x 16 outs
    int nb = blockIdx.x * 16;
#pragma unroll
    for (int i = 0; i < 8; i++) {
        int idx  = t + i * 256;      // 0..2047
        int node = idx >> 7, k = idx & 127;
        float v = (nb + node < n) ? g_out1[(nb + node) * D1 + k] : 0.f;
        xs[node * 132 + k] = fmaxf(v, 0.f);     // relu
    }
    __syncthreads();
    int ni = t >> 4;
    int o  = t & 15;
    float a0 = 0.f, a1 = 0.f, a2 = 0.f, a3 = 0.f;
#pragma unroll
    for (int k4 = 0; k4 < D1 / 4; k4 += 4) {
#pragma unroll
        for (int u = 0; u < 4; u++) {
            float4 w  = g_w2t4[(k4 + u) * NC + o];
            float4 xv = *(const float4*)&xs[ni * 132 + (k4 + u) * 4];
            float p = xv.x * w.x + xv.y * w.y + xv.z * w.z + xv.w * w.w;
            if (u == 0) a0 += p; else if (u == 1) a1 += p; else if (u == 2) a2 += p; else a3 += p;
        }
    }
    float acc = (a0 + a1) + (a2 + a3);
    int node = nb + ni;
    if (node < n) g_xw2h[node * NC + o] = __float2half(acc);
    float ps = acc * att_s[o];
    float pd = acc * att_d[o];
#pragma unroll
    for (int j = 8; j >= 1; j >>= 1) {
        ps += __shfl_xor_sync(0xffffffffu, ps, j);
        pd += __shfl_xor_sync(0xffffffffu, pd, j);
    }
    if (o == 0 && node < n) { g_asrc2[node] = ps; g_adst2[node] = pd; }
}

// ---------------- layer-2 fused softmax+aggregate (warp per dst) -------------
__global__ void k_edge2(const float* __restrict__ b2, float* __restrict__ out, int n) {
    int gt = blockIdx.x * blockDim.x + threadIdx.x;
    int d  = gt >> 5;
    if (d >= n) return;
    int lane = gt & 31;
    int beg = (int)g_off[d], end = (int)g_off[d + 1];
    float add = g_adst2[d];
    int half = lane >> 4;
    int c    = lane & 15;
    float acc = 0.f, s = 0.f;
    for (int base = beg; base < end; base += 32) {
        int myi = base + lane;
        float ev = 0.f;
        int msrc = 0;
        if (myi < end) {
            msrc = g_adj[myi];
            ev = __expf(lrelu(g_asrc2[msrc] + add));
        }
        s += ev;
        int cnt = min(32, end - base);
#pragma unroll 4
        for (int j = 0; j < cnt; j += 2) {
            int jj = j + half;                  // lanes 0-15 edge j, 16-31 edge j+1
            int   src = __shfl_sync(0xffffffffu, msrc, jj & 31);
            float e   = __shfl_sync(0xffffffffu, ev, jj & 31);
            if (jj < cnt)
                acc += __half2float(g_xw2h[src * NC + c]) * e;
        }
    }
#pragma unroll
    for (int o = 16; o >= 1; o >>= 1)
        s += __shfl_xor_sync(0xffffffffu, s, o);
    acc += __shfl_xor_sync(0xffffffffu, acc, 16);
    if (half == 0) {
        float r = 1.f / (s + 1e-16f);
        out[d * NC + c] = acc * r + b2[c];
    }
}

// ---------------- launcher ----------------------------------------------------
extern "C" void kernel_launch(void* const* d_in, const int* in_sizes, int n_in,
                              void* d_out, int out_size) {
    const float* x   = (const float*)d_in[0];
    const int*   ei  = (const int*)d_in[1];      // int32
    const float* w1  = (const float*)d_in[2];
    const float* as1 = (const float*)d_in[3];
    const float* ad1 = (const float*)d_in[4];
    const float* b1  = (const float*)d_in[5];
    const float* w2  = (const float*)d_in[6];
    const float* as2 = (const float*)d_in[7];
    const float* ad2 = (const float*)d_in[8];
    const float* b2  = (const float*)d_in[9];
    float* out = (float*)d_out;

    int n  = in_sizes[0] / FIN;     // 50000
    int E  = in_sizes[1] / 2;       // 1600000
    int ET = E + n;                 // 1650000

    // side stream for the CSR build; created fresh per call (kernel_launch runs
    // only during correctness + capture, never in the timed replays), never
    // destroyed (destroying a capture-participating stream would invalidate
    // the graph). No device memory is allocated by stream/event creation.
    cudaStream_t s1;
    cudaStreamCreateWithFlags(&s1, cudaStreamNonBlocking);
    cudaEvent_t e_fork, e_join;
    cudaEventCreateWithFlags(&e_fork, cudaEventDisableTiming);
    cudaEventCreateWithFlags(&e_join, cudaEventDisableTiming);

    // fork: CSR chain on s1 runs concurrently with prep+gemm1 on stream 0
    cudaEventRecord(e_fork, 0);
    cudaStreamWaitEvent(s1, e_fork, 0);

    k_hist<<<(ET + 255) / 256, 256, 0, s1>>>(ei, E, ET);
    k_scan<<<1, 1024, 0, s1>>>(n);
    k_scatter<<<(ET + 255) / 256, 256, 0, s1>>>(ei, E, ET);
    cudaEventRecord(e_join, s1);

    // main chain (independent of CSR)
    k_prep<<<(FIN * D1 + 255) / 256, 256>>>(w1, w2);
    k_gemm1<<<(n + 31) / 32, 256>>>(x, as1, ad1, n);

    // join: edge phase needs both chains
    cudaStreamWaitEvent(0, e_join, 0);

    k_edge1<<<(n * 32 + 255) / 256, 256>>>(b1, n);
    k_gemm2<<<(n + 15) / 16, 256>>>(as2, ad2, n);
    k_edge2<<<(n * 32 + 255) / 256, 256>>>(b2, out, n);
}

// round 10
// speedup vs baseline: 1.1560x; 1.1560x over previous
#include <cuda_runtime.h>
#include <cuda_fp16.h>

// Problem constants (fixed shapes for this problem)
#define Nn    50000
#define FIN   128
#define D1    128           // H1*C1
#define NC    16
#define EMAX  1600000
#define ETMAX (EMAX + Nn)

// ---------------- scratch (device globals; no allocation allowed) ------------
__device__ unsigned   g_w1f[8 * 16 * 32 * 2]; // w1 in mma B-fragment order (half2 as u32)
__device__ float4     g_w2t4[(D1 / 4) * NC];
__device__ __half     g_xh[Nn * FIN];         // fp16 copy of x
__device__ __half2    g_xw1h[Nn * 64];        // fp16 gather payload (layer 1)
__device__ float      g_out1[Nn * D1];
__device__ float      g_asrc1[Nn * 2];
__device__ float      g_adst1[Nn * 2];
__device__ __half     g_xw2h[Nn * NC];        // fp16 gather payload (layer 2)
__device__ float      g_asrc2[Nn];
__device__ float      g_adst2[Nn];
__device__ unsigned   g_cnt[Nn];              // invariant: zero at kernel_launch entry
__device__ unsigned   g_off[Nn + 1];
__device__ unsigned   g_cur[Nn];
__device__ int        g_adj[ETMAX];           // CSR by dst: src node ids

__device__ __forceinline__ float lrelu(float a) { return a > 0.f ? a : 0.2f * a; }

// ---------------- prep: w1 -> B-fragment repack, w2 repack -------------------
__global__ void k_prep(const float* __restrict__ w1, const float* __restrict__ w2) {
    int i = blockIdx.x * blockDim.x + threadIdx.x;
    if (i < 8 * 16 * 32 * 2) {
        int reg  = i & 1;
        int lane = (i >> 1) & 31;
        int nfg  = (i >> 6) & 15;
        int ks   = i >> 10;
        int nn = nfg * 8 + (lane >> 2);                 // output channel
        int k  = ks * 16 + (lane & 3) * 2 + reg * 8;    // input channel
        __half2 h = __floats2half2_rn(w1[nn * FIN + k], w1[nn * FIN + k + 1]);
        g_w1f[i] = *(unsigned*)&h;
    }
    if (i < NC * D1) {
        int o = i / D1, k = i % D1;                     // w2: [NC][D1]
        ((float*)g_w2t4)[((k >> 2) * NC + o) * 4 + (k & 3)] = w2[i];
    }
}

// ---------------- x -> fp16 ---------------------------------------------------
__global__ void k_xh(const float* __restrict__ x, int total4) {
    int i = blockIdx.x * blockDim.x + threadIdx.x;
    if (i >= total4) return;
    float4 v = ((const float4*)x)[i];
    __half2 h0 = __floats2half2_rn(v.x, v.y);
    __half2 h1 = __floats2half2_rn(v.z, v.w);
    uint2 pk = make_uint2(*(unsigned*)&h0, *(unsigned*)&h1);
    ((uint2*)g_xh)[i] = pk;
}

// ---------------- CSR build ---------------------------------------------------
__global__ void k_hist(const int* __restrict__ ei, int E, int ET) {
    int e = blockIdx.x * blockDim.x + threadIdx.x;
    if (e >= ET) return;
    int d = (e < E) ? ei[E + e] : (e - E);
    atomicAdd(&g_cnt[d], 1u);
}

// ------- layer-1 GEMM via fp16 HMMA + att1 dots + fp16 payload ---------------
// 64 nodes/block; 8 warps = 4 M-frags x 2 N-halves; N-half == attention head.
__global__ __launch_bounds__(256) void k_gemm1(const float* __restrict__ att_s,
                                               const float* __restrict__ att_d, int n) {
    int tid = threadIdx.x;
    int w = tid >> 5, t = tid & 31;
    int mfrag = w >> 1, nhalf = w & 1;
    int r = t >> 2, q = t & 3;
    int node0 = blockIdx.x * 64 + mfrag * 16 + r;
    int node1 = node0 + 8;
    int nl0 = min(node0, n - 1) * FIN;
    int nl1 = min(node1, n - 1) * FIN;

    float c[8][4];
#pragma unroll
    for (int nf = 0; nf < 8; nf++)
#pragma unroll
        for (int j = 0; j < 4; j++) c[nf][j] = 0.f;

#pragma unroll
    for (int ks = 0; ks < 8; ks++) {
        int kb = ks * 16 + q * 2;
        unsigned a0 = *(const unsigned*)&g_xh[nl0 + kb];
        unsigned a1 = *(const unsigned*)&g_xh[nl1 + kb];
        unsigned a2 = *(const unsigned*)&g_xh[nl0 + kb + 8];
        unsigned a3 = *(const unsigned*)&g_xh[nl1 + kb + 8];
#pragma unroll
        for (int nf = 0; nf < 8; nf++) {
            int nfg = nhalf * 8 + nf;
            uint2 b = *(const uint2*)&g_w1f[((ks * 16 + nfg) * 32 + t) * 2];
            asm volatile(
                "mma.sync.aligned.m16n8k16.row.col.f32.f16.f16.f32 "
                "{%0,%1,%2,%3}, {%4,%5,%6,%7}, {%8,%9}, {%0,%1,%2,%3};\n"
                : "+f"(c[nf][0]), "+f"(c[nf][1]), "+f"(c[nf][2]), "+f"(c[nf][3])
                : "r"(a0), "r"(a1), "r"(a2), "r"(a3), "r"(b.x), "r"(b.y));
        }
    }

    // epilogue: payload stores + per-head attention dots (head == nhalf)
    float ps0 = 0.f, pd0 = 0.f, ps1 = 0.f, pd1 = 0.f;
#pragma unroll
    for (int nf = 0; nf < 8; nf++) {
        int col = nhalf * 64 + nf * 8 + q * 2;
        float as0 = att_s[col], as1 = att_s[col + 1];
        float ad0 = att_d[col], ad1 = att_d[col + 1];
        ps0 += c[nf][0] * as0 + c[nf][1] * as1;
        pd0 += c[nf][0] * ad0 + c[nf][1] * ad1;
        ps1 += c[nf][2] * as0 + c[nf][3] * as1;
        pd1 += c[nf][2] * ad0 + c[nf][3] * ad1;
        int pidx = nhalf * 32 + nf * 4 + q;
        if (node0 < n) g_xw1h[node0 * 64 + pidx] = __floats2half2_rn(c[nf][0], c[nf][1]);
        if (node1 < n) g_xw1h[node1 * 64 + pidx] = __floats2half2_rn(c[nf][2], c[nf][3]);
    }
#pragma unroll
    for (int o = 1; o <= 2; o <<= 1) {
        ps0 += __shfl_xor_sync(0xffffffffu, ps0, o);
        pd0 += __shfl_xor_sync(0xffffffffu, pd0, o);
        ps1 += __shfl_xor_sync(0xffffffffu, ps1, o);
        pd1 += __shfl_xor_sync(0xffffffffu, pd1, o);
    }
    if (q == 0) {
        if (node0 < n) { g_asrc1[node0 * 2 + nhalf] = ps0; g_adst1[node0 * 2 + nhalf] = pd0; }
        if (node1 < n) { g_asrc1[node1 * 2 + nhalf] = ps1; g_adst1[node1 * 2 + nhalf] = pd1; }
    }
}

// -------- scan (+ re-zero g_cnt for next call) -------------------------------
__global__ void k_scan(int n) {
    __shared__ unsigned ssum[1024];
    int t = threadIdx.x;
    int chunk = (n + 1023) >> 10;
    int b = t * chunk;
    int e = min(b + chunk, n);
    unsigned sum = 0;
    for (int i = b; i < e; i++) sum += g_cnt[i];
    ssum[t] = sum;
    __syncthreads();
    for (int o = 1; o < 1024; o <<= 1) {
        unsigned v = (t >= o) ? ssum[t - o] : 0u;
        __syncthreads();
        ssum[t] += v;
        __syncthreads();
    }
    unsigned run = (t == 0) ? 0u : ssum[t - 1];
    for (int i = b; i < e; i++) {
        unsigned c = g_cnt[i];
        g_cnt[i] = 0u;                            // restore invariant
        g_off[i] = run;
        g_cur[i] = run;
        run += c;
    }
    if (t == 0) g_off[n] = ssum[1023];
}

__global__ void k_scatter(const int* __restrict__ ei, int E, int ET) {
    int e = blockIdx.x * blockDim.x + threadIdx.x;
    if (e >= ET) return;
    int s, d;
    if (e < E) { s = ei[e]; d = ei[E + e]; } else { s = d = e - E; }
    unsigned pos = atomicAdd(&g_cur[d], 1u);
    g_adj[pos] = s;
}

// ------- layer-1 fused softmax+aggregate: warp/dst, 16-edge pipelined chunks -
__global__ void k_edge1(const float* __restrict__ b1, int n) {
    int gt = blockIdx.x * blockDim.x + threadIdx.x;
    int d  = gt >> 5;
    if (d >= n) return;
    int lane = gt & 31, h = lane >> 4, sub = lane & 15;
    int beg = (int)g_off[d], end = (int)g_off[d + 1];
    float adh = g_adst1[d * 2 + h];
    float4 acc = make_float4(0.f, 0.f, 0.f, 0.f);
    float s = 0.f;
    // chunk 0: lanes 0-15 compute e(head0), lanes 16-31 e(head1), same 16 edges
    int base = beg;
    int msrc = 0; float ex = 0.f;
    {
        int i0 = base + sub;
        if (i0 < end) {
            msrc = g_adj[i0];
            ex = __expf(lrelu(g_asrc1[msrc * 2 + h] + adh));
        }
    }
    while (base < end) {
        int nbase = base + 16;
        int nsrc = 0; float nex = 0.f;
        if (nbase < end) {              // software-pipeline next chunk's dep chain
            int i1 = nbase + sub;
            if (i1 < end) {
                nsrc = g_adj[i1];
                nex = __expf(lrelu(g_asrc1[nsrc * 2 + h] + adh));
            }
        }
        s += ex;
        int cnt = min(16, end - base);
#pragma unroll 8
        for (int j = 0; j < cnt; j++) {
            int   src  = __shfl_sync(0xffffffffu, msrc, j);
            float coef = __shfl_sync(0xffffffffu, ex, j + (h << 4));
            uint2 p = *(const uint2*)&g_xw1h[src * 64 + lane * 2];
            float2 v01 = __half22float2(*(__half2*)&p.x);
            float2 v23 = __half22float2(*(__half2*)&p.y);
            acc.x += v01.x * coef; acc.y += v01.y * coef;
            acc.z += v23.x * coef; acc.w += v23.y * coef;
        }
        msrc = nsrc; ex = nex; base = nbase;
    }
#pragma unroll
    for (int o = 8; o >= 1; o >>= 1)    // per-half sums: lanes<16 -> s0, >=16 -> s1
        s += __shfl_xor_sync(0xffffffffu, s, o);
    float r = 1.f / (s + 1e-16f);
    float4 bb = *(const float4*)&b1[lane * 4];
    *(float4*)&g_out1[d * D1 + lane * 4] =
        make_float4(acc.x * r + bb.x, acc.y * r + bb.y, acc.z * r + bb.z, acc.w * r + bb.w);
}

// ----- layer-2 GEMM (16 nodes/block, relu fused on load) + att2 dots ---------
__global__ __launch_bounds__(256) void k_gemm2(const float* __restrict__ att_s,
                                               const float* __restrict__ att_d, int n) {
    __shared__ float xs[16 * 132];
    int t  = threadIdx.x;            // 256 threads = 16 nodes x 16 outs
    int nb = blockIdx.x * 16;
#pragma unroll
    for (int i = 0; i < 8; i++) {
        int idx  = t + i * 256;      // 0..2047
        int node = idx >> 7, k = idx & 127;
        float v = (nb + node < n) ? g_out1[(nb + node) * D1 + k] : 0.f;
        xs[node * 132 + k] = fmaxf(v, 0.f);     // relu
    }
    __syncthreads();
    int ni = t >> 4;
    int o  = t & 15;
    float a0 = 0.f, a1 = 0.f, a2 = 0.f, a3 = 0.f;
#pragma unroll
    for (int k4 = 0; k4 < D1 / 4; k4 += 4) {
#pragma unroll
        for (int u = 0; u < 4; u++) {
            float4 w  = g_w2t4[(k4 + u) * NC + o];
            float4 xv = *(const float4*)&xs[ni * 132 + (k4 + u) * 4];
            float p = xv.x * w.x + xv.y * w.y + xv.z * w.z + xv.w * w.w;
            if (u == 0) a0 += p; else if (u == 1) a1 += p; else if (u == 2) a2 += p; else a3 += p;
        }
    }
    float acc = (a0 + a1) + (a2 + a3);
    int node = nb + ni;
    if (node < n) g_xw2h[node * NC + o] = __float2half(acc);
    float ps = acc * att_s[o];
    float pd = acc * att_d[o];
#pragma unroll
    for (int j = 8; j >= 1; j >>= 1) {
        ps += __shfl_xor_sync(0xffffffffu, ps, j);
        pd += __shfl_xor_sync(0xffffffffu, pd, j);
    }
    if (o == 0 && node < n) { g_asrc2[node] = ps; g_adst2[node] = pd; }
}

// ---------------- layer-2 fused softmax+aggregate (warp per dst) -------------
__global__ void k_edge2(const float* __restrict__ b2, float* __restrict__ out, int n) {
    int gt = blockIdx.x * blockDim.x + threadIdx.x;
    int d  = gt >> 5;
    if (d >= n) return;
    int lane = gt & 31;
    int beg = (int)g_off[d], end = (int)g_off[d + 1];
    float add = g_adst2[d];
    int half = lane >> 4;
    int c    = lane & 15;
    float acc = 0.f, s = 0.f;
    for (int base = beg; base < end; base += 32) {
        int myi = base + lane;
        float ev = 0.f;
        int msrc = 0;
        if (myi < end) {
            msrc = g_adj[myi];
            ev = __expf(lrelu(g_asrc2[msrc] + add));
        }
        s += ev;
        int cnt = min(32, end - base);
#pragma unroll 4
        for (int j = 0; j < cnt; j += 2) {
            int jj = j + half;                  // lanes 0-15 edge j, 16-31 edge j+1
            int   src = __shfl_sync(0xffffffffu, msrc, jj & 31);
            float e   = __shfl_sync(0xffffffffu, ev, jj & 31);
            if (jj < cnt)
                acc += __half2float(g_xw2h[src * NC + c]) * e;
        }
    }
#pragma unroll
    for (int o = 16; o >= 1; o >>= 1)
        s += __shfl_xor_sync(0xffffffffu, s, o);
    acc += __shfl_xor_sync(0xffffffffu, acc, 16);
    if (half == 0) {
        float r = 1.f / (s + 1e-16f);
        out[d * NC + c] = acc * r + b2[c];
    }
}

// ---------------- launcher ----------------------------------------------------
extern "C" void kernel_launch(void* const* d_in, const int* in_sizes, int n_in,
                              void* d_out, int out_size) {
    const float* x   = (const float*)d_in[0];
    const int*   ei  = (const int*)d_in[1];      // int32
    const float* w1  = (const float*)d_in[2];
    const float* as1 = (const float*)d_in[3];
    const float* ad1 = (const float*)d_in[4];
    const float* b1  = (const float*)d_in[5];
    const float* w2  = (const float*)d_in[6];
    const float* as2 = (const float*)d_in[7];
    const float* ad2 = (const float*)d_in[8];
    const float* b2  = (const float*)d_in[9];
    float* out = (float*)d_out;

    int n  = in_sizes[0] / FIN;     // 50000
    int E  = in_sizes[1] / 2;       // 1600000
    int ET = E + n;                 // 1650000

    // 0: weight repacks (w1 -> mma fragments, w2 -> float4)
    k_prep<<<(8 * 16 * 32 * 2 + 255) / 256, 256>>>(w1, w2);
    // 1: x -> fp16
    k_xh<<<(n * FIN / 4 + 255) / 256, 256>>>(x, n * FIN / 4);
    // 2: CSR histogram
    k_hist<<<(ET + 255) / 256, 256>>>(ei, E, ET);
    // 3 (profiled): tensor-core GEMM1 + att1 dots + payload
    k_gemm1<<<(n + 63) / 64, 256>>>(as1, ad1, n);
    // CSR scan + scatter
    k_scan<<<1, 1024>>>(n);
    k_scatter<<<(ET + 255) / 256, 256>>>(ei, E, ET);
    // layer-1 softmax+aggregate
    k_edge1<<<(n * 32 + 255) / 256, 256>>>(b1, n);
    // layer 2
    k_gemm2<<<(n + 15) / 16, 256>>>(as2, ad2, n);
    k_edge2<<<(n * 32 + 255) / 256, 256>>>(b2, out, n);
}